// round 15
// baseline (speedup 1.0000x reference)
#include <cuda_runtime.h>
#include <cuda_fp16.h>

#define NN 50000
#define EE 800000
#define DD 128

// ---------------- device scratch (no allocs allowed) ----------------
__device__ __half2  g_hh[NN * 64];   // current layer input, fp16, pre-scaled by norm_src
__device__ __half2  g_agg[NN * 64];  // SpMM output, fp16 (already * norm_dst)
__device__ unsigned g_wt[3 * 8192];  // W1..W3 as fp16, n-major: wt[l][n][k] (half2 over k)
__device__ int      g_deg[2 * NN];   // [0,NN)=deg_out, [NN,2NN)=deg_in
__device__ float    g_norm_src[NN];
__device__ float    g_norm_dst[NN];
__device__ int      g_row_ptr[NN + 1];
__device__ int      g_cursor[NN];
__device__ int      g_col[EE];       // src ids grouped by dst
__device__ int      g_bsum[64];

// ---------------- setup 1: wconv (blocks 0..95) + degree (rest), independent ----------------
#define WCONV_BLOCKS 96                       // 3*8192 / 256
#define DEG_BLOCKS   ((EE / 8 + 255) / 256)   // 8 edges per thread

__global__ void k_setup1(const int4* __restrict__ src4, const int4* __restrict__ dst4,
                         const float* __restrict__ W1, const float* __restrict__ W2,
                         const float* __restrict__ W3) {
    int bid = blockIdx.x;
    if (bid < WCONV_BLOCKS) {
        int idx = bid * 256 + threadIdx.x;     // 0 .. 3*8192-1
        int l   = idx >> 13;
        int rem = idx & 8191;
        int kp  = rem >> 7;
        int n   = rem & 127;
        const float* W = (l == 0) ? W1 : (l == 1) ? W2 : W3;
        __half2 h = __floats2half2_rn(W[(2 * kp) * 128 + n], W[(2 * kp + 1) * 128 + n]);
        g_wt[l * 8192 + n * 64 + kp] = *(unsigned*)&h;
    } else {
        int t = (bid - WCONV_BLOCKS) * 256 + threadIdx.x;
        if (t < EE / 8) {
            int4 s0 = src4[t * 2],     d0 = dst4[t * 2];
            int4 s1 = src4[t * 2 + 1], d1 = dst4[t * 2 + 1];
            atomicAdd(&g_deg[s0.x], 1); atomicAdd(&g_deg[s0.y], 1);
            atomicAdd(&g_deg[s0.z], 1); atomicAdd(&g_deg[s0.w], 1);
            atomicAdd(&g_deg[s1.x], 1); atomicAdd(&g_deg[s1.y], 1);
            atomicAdd(&g_deg[s1.z], 1); atomicAdd(&g_deg[s1.w], 1);
            atomicAdd(&g_deg[NN + d0.x], 1); atomicAdd(&g_deg[NN + d0.y], 1);
            atomicAdd(&g_deg[NN + d0.z], 1); atomicAdd(&g_deg[NN + d0.w], 1);
            atomicAdd(&g_deg[NN + d1.x], 1); atomicAdd(&g_deg[NN + d1.y], 1);
            atomicAdd(&g_deg[NN + d1.z], 1); atomicAdd(&g_deg[NN + d1.w], 1);
        }
    }
}

// ---------------- scan phase 1 over deg_in (1024/block) + norms (fused) ----------------
__global__ void k_scan1n() {
    __shared__ int warp_sums[32];
    const int tid = threadIdx.x;
    int i = blockIdx.x * 1024 + tid;
    int v = 0;
    if (i < NN) {
        int dout = g_deg[i];      if (dout < 1) dout = 1;
        int din  = g_deg[NN + i];
        v = din;
        if (din < 1) din = 1;
        g_norm_src[i] = rsqrtf((float)dout);
        g_norm_dst[i] = rsqrtf((float)din);
    }
    int x = v;
    #pragma unroll
    for (int off = 1; off < 32; off <<= 1) {
        int y = __shfl_up_sync(0xffffffffu, x, off);
        if ((tid & 31) >= off) x += y;
    }
    if ((tid & 31) == 31) warp_sums[tid >> 5] = x;
    __syncthreads();
    if (tid < 32) {
        int w = warp_sums[tid];
        #pragma unroll
        for (int off = 1; off < 32; off <<= 1) {
            int y = __shfl_up_sync(0xffffffffu, w, off);
            if (tid >= off) w += y;
        }
        warp_sums[tid] = w;
    }
    __syncthreads();
    int warp_off = (tid >= 32) ? warp_sums[(tid >> 5) - 1] : 0;
    int incl = x + warp_off;
    if (i < NN) g_row_ptr[i] = incl - v;       // local exclusive
    if (tid == 1023) g_bsum[blockIdx.x] = incl;
}

// ---------------- setup 2: scan3 (blocks 0..195) + h0 (rest); both depend on scan1n ----------------
#define SCAN3_BLOCKS 196                      // ceil(NN/256)
#define H0_BLOCKS    ((NN * 16 + 255) / 256)  // 3125

__global__ void k_setup2(const int* __restrict__ batch, const float4* __restrict__ emb) {
    int bid = blockIdx.x;
    if (bid < SCAN3_BLOCKS) {
        __shared__ int s_off;
        const int tid = threadIdx.x;
        const int grp = bid >> 2;
        if (tid < 32) {
            int a = (tid < grp)      ? g_bsum[tid]      : 0;
            int b = (tid + 32 < grp) ? g_bsum[tid + 32] : 0;
            int s = a + b;
            #pragma unroll
            for (int off = 16; off > 0; off >>= 1)
                s += __shfl_down_sync(0xffffffffu, s, off);
            if (tid == 0) s_off = s;
        }
        __syncthreads();
        int i = bid * 256 + tid;
        if (i < NN) {
            int val = g_row_ptr[i] + s_off;
            g_row_ptr[i] = val;
            g_cursor[i]  = val;
        }
        if (i == 0) g_row_ptr[NN] = EE;
    } else {
        int idx = (bid - SCAN3_BLOCKS) * 256 + threadIdx.x;
        if (idx >= NN * 16) return;
        int i = idx >> 4, q = idx & 15;
        float ns = g_norm_src[i];
        const float4* row = emb + (size_t)batch[i] * 32;
        float4 v0 = row[q * 2];
        float4 v1 = row[q * 2 + 1];
        __half2 p0 = __floats2half2_rn(v0.x * ns, v0.y * ns);
        __half2 p1 = __floats2half2_rn(v0.z * ns, v0.w * ns);
        __half2 p2 = __floats2half2_rn(v1.x * ns, v1.y * ns);
        __half2 p3 = __floats2half2_rn(v1.z * ns, v1.w * ns);
        uint4 o = make_uint4(*(unsigned*)&p0, *(unsigned*)&p1,
                             *(unsigned*)&p2, *(unsigned*)&p3);
        ((uint4*)g_hh)[idx] = o;
    }
}

// ---------------- fill: 8 edges per thread ----------------
__global__ void k_fill(const int4* __restrict__ src4, const int4* __restrict__ dst4) {
    int t = blockIdx.x * blockDim.x + threadIdx.x;
    if (t < EE / 8) {
        int4 s0 = src4[t * 2],     d0 = dst4[t * 2];
        int4 s1 = src4[t * 2 + 1], d1 = dst4[t * 2 + 1];
        g_col[atomicAdd(&g_cursor[d0.x], 1)] = s0.x;
        g_col[atomicAdd(&g_cursor[d0.y], 1)] = s0.y;
        g_col[atomicAdd(&g_cursor[d0.z], 1)] = s0.z;
        g_col[atomicAdd(&g_cursor[d0.w], 1)] = s0.w;
        g_col[atomicAdd(&g_cursor[d1.x], 1)] = s1.x;
        g_col[atomicAdd(&g_cursor[d1.y], 1)] = s1.y;
        g_col[atomicAdd(&g_cursor[d1.z], 1)] = s1.z;
        g_col[atomicAdd(&g_cursor[d1.w], 1)] = s1.w;
    }
}

// ---------------- SpMM: warp per dst row; fp16 pairwise tree, fp32 accumulate ----------------
// Per 8-edge block: each half-warp sums its 4 edges with a 2-level HADD2 tree
// (noise ~= fp16 storage rounding), converts once to fp32, accumulates.
__global__ void k_spmm() {
    int warp = (blockIdx.x * blockDim.x + threadIdx.x) >> 5;
    int lane = threadIdx.x & 31;
    if (warp >= NN) return;
    const uint4* hp = (const uint4*)g_hh;      // row stride = 16 uint4 (128 halves)
    const int hl  = lane & 15;
    const int sel = lane >> 4;
    int beg = g_row_ptr[warp];
    int end = g_row_ptr[warp + 1];
    float acc[8];
    #pragma unroll
    for (int k = 0; k < 8; k++) acc[k] = 0.f;

    for (int j0 = beg; j0 < end; j0 += 32) {
        int c = 0;
        if (j0 + lane < end) c = g_col[j0 + lane];
        int n = end - j0; if (n > 32) n = 32;
        int t = 0;
        // 8 edges per iteration: half-warp sel handles edges {t+sel, t+2+sel, t+4+sel, t+6+sel}
        for (; t + 7 < n; t += 8) {
            int s0 = __shfl_sync(0xffffffffu, c, t + sel);
            int s1 = __shfl_sync(0xffffffffu, c, t + 2 + sel);
            int s2 = __shfl_sync(0xffffffffu, c, t + 4 + sel);
            int s3 = __shfl_sync(0xffffffffu, c, t + 6 + sel);
            uint4 u0 = hp[s0 * 16 + hl];
            uint4 u1 = hp[s1 * 16 + hl];
            uint4 u2 = hp[s2 * 16 + hl];
            uint4 u3 = hp[s3 * 16 + hl];
            __half2 vx = __hadd2(__hadd2(*(__half2*)&u0.x, *(__half2*)&u1.x),
                                 __hadd2(*(__half2*)&u2.x, *(__half2*)&u3.x));
            __half2 vy = __hadd2(__hadd2(*(__half2*)&u0.y, *(__half2*)&u1.y),
                                 __hadd2(*(__half2*)&u2.y, *(__half2*)&u3.y));
            __half2 vz = __hadd2(__hadd2(*(__half2*)&u0.z, *(__half2*)&u1.z),
                                 __hadd2(*(__half2*)&u2.z, *(__half2*)&u3.z));
            __half2 vw = __hadd2(__hadd2(*(__half2*)&u0.w, *(__half2*)&u1.w),
                                 __hadd2(*(__half2*)&u2.w, *(__half2*)&u3.w));
            float2 f;
            f = __half22float2(vx); acc[0] += f.x; acc[1] += f.y;
            f = __half22float2(vy); acc[2] += f.x; acc[3] += f.y;
            f = __half22float2(vz); acc[4] += f.x; acc[5] += f.y;
            f = __half22float2(vw); acc[6] += f.x; acc[7] += f.y;
        }
        // remainder: 2 edges per iteration (exact fp32 path)
        for (; t < n; t += 2) {
            int e = t + sel;
            int s = __shfl_sync(0xffffffffu, c, e < 31 ? e : 31);
            if (e < n) {
                uint4 u = hp[s * 16 + hl];
                float2 f;
                f = __half22float2(*(__half2*)&u.x); acc[0] += f.x; acc[1] += f.y;
                f = __half22float2(*(__half2*)&u.y); acc[2] += f.x; acc[3] += f.y;
                f = __half22float2(*(__half2*)&u.z); acc[4] += f.x; acc[5] += f.y;
                f = __half22float2(*(__half2*)&u.w); acc[6] += f.x; acc[7] += f.y;
            }
        }
    }
    #pragma unroll
    for (int k = 0; k < 8; k++) acc[k] += __shfl_xor_sync(0xffffffffu, acc[k], 16);

    if (sel == 0) {
        float nd = g_norm_dst[warp];
        __half2 p0 = __floats2half2_rn(acc[0] * nd, acc[1] * nd);
        __half2 p1 = __floats2half2_rn(acc[2] * nd, acc[3] * nd);
        __half2 p2 = __floats2half2_rn(acc[4] * nd, acc[5] * nd);
        __half2 p3 = __floats2half2_rn(acc[6] * nd, acc[7] * nd);
        uint4 o = make_uint4(*(unsigned*)&p0, *(unsigned*)&p1,
                             *(unsigned*)&p2, *(unsigned*)&p3);
        ((uint4*)g_agg)[warp * 16 + hl] = o;
    }
}

// ---------------- FP16 tensor-core GEMM: out = relu(A @ W + b) [* rowscale] ----------------
#define ASH 68   // half2 per A smem row
#define BSH 66   // half2 per B smem row
#define GEMM_SMEM ((128 * ASH + 128 * BSH) * 4)   // 68608 B

template <bool HALF_OUT>
__global__ __launch_bounds__(256, 2) void k_gemm_f16(
    const uint4* __restrict__ A4, const uint2* __restrict__ WT2,
    const float* __restrict__ bias, const float* __restrict__ rowscale,
    void* __restrict__ outp, int M)
{
    extern __shared__ unsigned smem[];
    unsigned* As = smem;                  // [128][ASH] half2
    unsigned* Bs = smem + 128 * ASH;      // [128][BSH] half2, n-major

    const int tid  = threadIdx.x;
    const int wid  = tid >> 5;
    const int lane = tid & 31;
    const int g = lane >> 2;
    const int c = lane & 3;
    const int wm = (wid & 3) * 32;
    const int wn = (wid >> 2) * 64;
    const int row0 = blockIdx.x * 128;

    #pragma unroll
    for (int l = 0; l < 8; l++) {
        int idx = l * 256 + tid;
        int r = idx >> 4;
        int q = idx & 15;
        uint4 u = make_uint4(0u, 0u, 0u, 0u);
        if (row0 + r < M) u = A4[(row0 + r) * 16 + q];
        *(uint4*)&As[r * ASH + q * 4] = u;
    }
    #pragma unroll
    for (int l = 0; l < 16; l++) {
        int idx = l * 256 + tid;
        int n = idx >> 5;
        int q = idx & 31;
        uint2 u = WT2[n * 32 + q];
        *(uint2*)&Bs[n * BSH + q * 2] = u;
    }
    __syncthreads();

    float acc[2][8][4];
    #pragma unroll
    for (int i = 0; i < 2; i++)
        #pragma unroll
        for (int j = 0; j < 8; j++)
            #pragma unroll
            for (int k = 0; k < 4; k++) acc[i][j][k] = 0.f;

    #pragma unroll
    for (int s = 0; s < 8; s++) {
        const int ko = s * 8;
        unsigned a[2][4];
        #pragma unroll
        for (int mt = 0; mt < 2; mt++) {
            int r = wm + mt * 16 + g;
            a[mt][0] = As[r * ASH + ko + c];
            a[mt][1] = As[(r + 8) * ASH + ko + c];
            a[mt][2] = As[r * ASH + ko + c + 4];
            a[mt][3] = As[(r + 8) * ASH + ko + c + 4];
        }
        #pragma unroll
        for (int nt = 0; nt < 8; nt++) {
            int col = wn + nt * 8 + g;
            unsigned b0 = Bs[col * BSH + ko + c];
            unsigned b1 = Bs[col * BSH + ko + c + 4];
            #pragma unroll
            for (int mt = 0; mt < 2; mt++) {
                asm volatile(
                    "mma.sync.aligned.m16n8k16.row.col.f32.f16.f16.f32 "
                    "{%0,%1,%2,%3}, {%4,%5,%6,%7}, {%8,%9}, {%0,%1,%2,%3};\n"
                    : "+f"(acc[mt][nt][0]), "+f"(acc[mt][nt][1]),
                      "+f"(acc[mt][nt][2]), "+f"(acc[mt][nt][3])
                    : "r"(a[mt][0]), "r"(a[mt][1]), "r"(a[mt][2]), "r"(a[mt][3]),
                      "r"(b0), "r"(b1));
            }
        }
    }

    const int c2 = c * 2;
    #pragma unroll
    for (int nt = 0; nt < 8; nt++) {
        int col = wn + nt * 8 + c2;
        float bi0 = bias[col], bi1 = bias[col + 1];
        #pragma unroll
        for (int mt = 0; mt < 2; mt++) {
            int r = row0 + wm + mt * 16 + g;
            if (r < M) {
                float rs = rowscale ? rowscale[r] : 1.0f;
                float ox = fmaxf(acc[mt][nt][0] + bi0, 0.f) * rs;
                float oy = fmaxf(acc[mt][nt][1] + bi1, 0.f) * rs;
                if (HALF_OUT)
                    ((__half2*)outp)[r * 64 + (col >> 1)] = __floats2half2_rn(ox, oy);
                else
                    ((float2*)outp)[r * 64 + (col >> 1)] = make_float2(ox, oy);
            }
            int r2 = r + 8;
            if (r2 < M) {
                float rs = rowscale ? rowscale[r2] : 1.0f;
                float ox = fmaxf(acc[mt][nt][2] + bi0, 0.f) * rs;
                float oy = fmaxf(acc[mt][nt][3] + bi1, 0.f) * rs;
                if (HALF_OUT)
                    ((__half2*)outp)[r2 * 64 + (col >> 1)] = __floats2half2_rn(ox, oy);
                else
                    ((float2*)outp)[r2 * 64 + (col >> 1)] = make_float2(ox, oy);
            }
        }
    }
}

// ---------------- launch (single stream) ----------------
extern "C" void kernel_launch(void* const* d_in, const int* in_sizes, int n_in,
                              void* d_out, int out_size)
{
    const int*   batch = (const int*)d_in[0];
    const int*   src   = (const int*)d_in[1];
    const int*   dst   = (const int*)d_in[2];
    const float* emb   = (const float*)d_in[3];
    const float* W1    = (const float*)d_in[4];
    const float* b1    = (const float*)d_in[5];
    const float* W2    = (const float*)d_in[6];
    const float* b2    = (const float*)d_in[7];
    const float* W3    = (const float*)d_in[8];
    const float* b3    = (const float*)d_in[9];

    __half2* hbuf;   cudaGetSymbolAddress((void**)&hbuf, g_hh);
    __half2* aggbuf; cudaGetSymbolAddress((void**)&aggbuf, g_agg);
    unsigned* wt;    cudaGetSymbolAddress((void**)&wt, g_wt);
    int* degp;       cudaGetSymbolAddress((void**)&degp, g_deg);
    float* nsrc;     cudaGetSymbolAddress((void**)&nsrc, g_norm_src);

    cudaFuncSetAttribute(k_gemm_f16<true>,
                         cudaFuncAttributeMaxDynamicSharedMemorySize, GEMM_SMEM);
    cudaFuncSetAttribute(k_gemm_f16<false>,
                         cudaFuncAttributeMaxDynamicSharedMemorySize, GEMM_SMEM);

    const int scan_blocks = (NN + 1023) / 1024;   // 49

    cudaMemsetAsync(degp, 0, 2 * NN * sizeof(int), 0);
    k_setup1<<<WCONV_BLOCKS + DEG_BLOCKS, 256>>>((const int4*)src, (const int4*)dst,
                                                 W1, W2, W3);
    k_scan1n<<<scan_blocks, 1024>>>();
    k_setup2<<<SCAN3_BLOCKS + H0_BLOCKS, 256>>>(batch, (const float4*)emb);
    k_fill<<<(EE / 8 + 255) / 256, 256>>>((const int4*)src, (const int4*)dst);

    const int gemm_grid = (NN + 127) / 128;       // 391
    const int spmm_grid = (NN + 7) / 8;

    // layer 1
    k_spmm<<<spmm_grid, 256>>>();
    k_gemm_f16<true><<<gemm_grid, 256, GEMM_SMEM>>>((const uint4*)aggbuf,
                                                    (const uint2*)wt, b1,
                                                    nsrc, hbuf, NN);
    // layer 2
    k_spmm<<<spmm_grid, 256>>>();
    k_gemm_f16<true><<<gemm_grid, 256, GEMM_SMEM>>>((const uint4*)aggbuf,
                                                    (const uint2*)(wt + 8192), b2,
                                                    nsrc, hbuf, NN);
    // layer 3 -> d_out (fp32, no rowscale)
    k_spmm<<<spmm_grid, 256>>>();
    k_gemm_f16<false><<<gemm_grid, 256, GEMM_SMEM>>>((const uint4*)aggbuf,
                                                     (const uint2*)(wt + 16384), b3,
                                                     nullptr, d_out, NN);
}

// round 16
// speedup vs baseline: 1.0435x; 1.0435x over previous
#include <cuda_runtime.h>
#include <cuda_fp16.h>

#define NN 50000
#define EE 800000
#define DD 128

// ---------------- device scratch (no allocs allowed) ----------------
__device__ __half2  g_hh[NN * 64];   // current layer input, fp16, pre-scaled by norm_src
__device__ __half2  g_agg[NN * 64];  // SpMM output, fp16 (already * norm_dst)
__device__ unsigned g_wt[3 * 8192];  // W1..W3 as fp16, n-major: wt[l][n][k] (half2 over k)
__device__ int      g_deg[2 * NN];   // [0,NN)=deg_out, [NN,2NN)=deg_in
__device__ float    g_norm_src[NN];
__device__ float    g_norm_dst[NN];
__device__ int      g_row_ptr[NN + 1];
__device__ int      g_cursor[NN];
__device__ int      g_col[EE];       // src ids grouped by dst
__device__ int      g_bsum[64];

// ---------------- setup 1: wconv (blocks 0..95) + degree (rest), independent ----------------
#define WCONV_BLOCKS 96                       // 3*8192 / 256
#define DEG_BLOCKS   ((EE / 8 + 255) / 256)   // 8 edges per thread

__global__ void k_setup1(const int4* __restrict__ src4, const int4* __restrict__ dst4,
                         const float* __restrict__ W1, const float* __restrict__ W2,
                         const float* __restrict__ W3) {
    int bid = blockIdx.x;
    if (bid < WCONV_BLOCKS) {
        int idx = bid * 256 + threadIdx.x;     // 0 .. 3*8192-1
        int l   = idx >> 13;
        int rem = idx & 8191;
        int kp  = rem >> 7;
        int n   = rem & 127;
        const float* W = (l == 0) ? W1 : (l == 1) ? W2 : W3;
        __half2 h = __floats2half2_rn(W[(2 * kp) * 128 + n], W[(2 * kp + 1) * 128 + n]);
        g_wt[l * 8192 + n * 64 + kp] = *(unsigned*)&h;
    } else {
        int t = (bid - WCONV_BLOCKS) * 256 + threadIdx.x;
        if (t < EE / 8) {
            int4 s0 = src4[t * 2],     d0 = dst4[t * 2];
            int4 s1 = src4[t * 2 + 1], d1 = dst4[t * 2 + 1];
            atomicAdd(&g_deg[s0.x], 1); atomicAdd(&g_deg[s0.y], 1);
            atomicAdd(&g_deg[s0.z], 1); atomicAdd(&g_deg[s0.w], 1);
            atomicAdd(&g_deg[s1.x], 1); atomicAdd(&g_deg[s1.y], 1);
            atomicAdd(&g_deg[s1.z], 1); atomicAdd(&g_deg[s1.w], 1);
            atomicAdd(&g_deg[NN + d0.x], 1); atomicAdd(&g_deg[NN + d0.y], 1);
            atomicAdd(&g_deg[NN + d0.z], 1); atomicAdd(&g_deg[NN + d0.w], 1);
            atomicAdd(&g_deg[NN + d1.x], 1); atomicAdd(&g_deg[NN + d1.y], 1);
            atomicAdd(&g_deg[NN + d1.z], 1); atomicAdd(&g_deg[NN + d1.w], 1);
        }
    }
}

// ---------------- scan phase 1 over deg_in (1024/block) + norms (fused) ----------------
__global__ void k_scan1n() {
    __shared__ int warp_sums[32];
    const int tid = threadIdx.x;
    int i = blockIdx.x * 1024 + tid;
    int v = 0;
    if (i < NN) {
        int dout = g_deg[i];      if (dout < 1) dout = 1;
        int din  = g_deg[NN + i];
        v = din;
        if (din < 1) din = 1;
        g_norm_src[i] = rsqrtf((float)dout);
        g_norm_dst[i] = rsqrtf((float)din);
    }
    int x = v;
    #pragma unroll
    for (int off = 1; off < 32; off <<= 1) {
        int y = __shfl_up_sync(0xffffffffu, x, off);
        if ((tid & 31) >= off) x += y;
    }
    if ((tid & 31) == 31) warp_sums[tid >> 5] = x;
    __syncthreads();
    if (tid < 32) {
        int w = warp_sums[tid];
        #pragma unroll
        for (int off = 1; off < 32; off <<= 1) {
            int y = __shfl_up_sync(0xffffffffu, w, off);
            if (tid >= off) w += y;
        }
        warp_sums[tid] = w;
    }
    __syncthreads();
    int warp_off = (tid >= 32) ? warp_sums[(tid >> 5) - 1] : 0;
    int incl = x + warp_off;
    if (i < NN) g_row_ptr[i] = incl - v;       // local exclusive
    if (tid == 1023) g_bsum[blockIdx.x] = incl;
}

// ---------------- scan phase 2: add group offsets ----------------
__global__ void k_scan3() {
    __shared__ int s_off;
    const int tid = threadIdx.x;
    const int grp = blockIdx.x >> 2;
    if (tid < 32) {
        int a = (tid < grp)      ? g_bsum[tid]      : 0;
        int b = (tid + 32 < grp) ? g_bsum[tid + 32] : 0;
        int s = a + b;
        #pragma unroll
        for (int off = 16; off > 0; off >>= 1)
            s += __shfl_down_sync(0xffffffffu, s, off);
        if (tid == 0) s_off = s;
    }
    __syncthreads();
    int i = blockIdx.x * 256 + tid;
    if (i < NN) {
        int val = g_row_ptr[i] + s_off;
        g_row_ptr[i] = val;
        g_cursor[i]  = val;
    }
    if (i == 0) g_row_ptr[NN] = EE;
}

// ---------------- merged: fill (blocks 0..FILL-1) + h0 (rest) ----------------
#define FILL_BLOCKS ((EE / 8 + 255) / 256)     // 391
#define H0_BLOCKS   ((NN * 16 + 255) / 256)    // 3125

__global__ void k_h0fill(const int* __restrict__ batch, const float4* __restrict__ emb,
                         const int4* __restrict__ src4, const int4* __restrict__ dst4) {
    int bid = blockIdx.x;
    if (bid < FILL_BLOCKS) {
        int t = bid * 256 + threadIdx.x;
        if (t < EE / 8) {
            int4 s0 = src4[t * 2],     d0 = dst4[t * 2];
            int4 s1 = src4[t * 2 + 1], d1 = dst4[t * 2 + 1];
            g_col[atomicAdd(&g_cursor[d0.x], 1)] = s0.x;
            g_col[atomicAdd(&g_cursor[d0.y], 1)] = s0.y;
            g_col[atomicAdd(&g_cursor[d0.z], 1)] = s0.z;
            g_col[atomicAdd(&g_cursor[d0.w], 1)] = s0.w;
            g_col[atomicAdd(&g_cursor[d1.x], 1)] = s1.x;
            g_col[atomicAdd(&g_cursor[d1.y], 1)] = s1.y;
            g_col[atomicAdd(&g_cursor[d1.z], 1)] = s1.z;
            g_col[atomicAdd(&g_cursor[d1.w], 1)] = s1.w;
        }
    } else {
        int idx = (bid - FILL_BLOCKS) * 256 + threadIdx.x;
        if (idx >= NN * 16) return;
        int i = idx >> 4, q = idx & 15;
        float ns = g_norm_src[i];
        const float4* row = emb + (size_t)batch[i] * 32;
        float4 v0 = row[q * 2];
        float4 v1 = row[q * 2 + 1];
        __half2 p0 = __floats2half2_rn(v0.x * ns, v0.y * ns);
        __half2 p1 = __floats2half2_rn(v0.z * ns, v0.w * ns);
        __half2 p2 = __floats2half2_rn(v1.x * ns, v1.y * ns);
        __half2 p3 = __floats2half2_rn(v1.z * ns, v1.w * ns);
        uint4 o = make_uint4(*(unsigned*)&p0, *(unsigned*)&p1,
                             *(unsigned*)&p2, *(unsigned*)&p3);
        ((uint4*)g_hh)[idx] = o;
    }
}

// ---------------- SpMM: R13 tiling; one-level fp16 pairing, fp32 accumulate ----------------
__global__ void k_spmm() {
    int warp = (blockIdx.x * blockDim.x + threadIdx.x) >> 5;
    int lane = threadIdx.x & 31;
    if (warp >= NN) return;
    const uint4* hp = (const uint4*)g_hh;      // row stride = 16 uint4 (128 halves)
    const int hl  = lane & 15;
    const int sel = lane >> 4;
    int beg = g_row_ptr[warp];
    int end = g_row_ptr[warp + 1];
    float acc[8];
    #pragma unroll
    for (int k = 0; k < 8; k++) acc[k] = 0.f;

    for (int j0 = beg; j0 < end; j0 += 32) {
        int c = 0;
        if (j0 + lane < end) c = g_col[j0 + lane];
        int n = end - j0; if (n > 32) n = 32;
        int t = 0;
        // 4 edges per iteration: each half-warp loads 2 rows, pairs them in fp16
        for (; t + 3 < n; t += 4) {
            int s0 = __shfl_sync(0xffffffffu, c, t + sel);
            int s1 = __shfl_sync(0xffffffffu, c, t + 2 + sel);
            uint4 u0 = hp[s0 * 16 + hl];
            uint4 u1 = hp[s1 * 16 + hl];
            __half2 vx = __hadd2(*(__half2*)&u0.x, *(__half2*)&u1.x);
            __half2 vy = __hadd2(*(__half2*)&u0.y, *(__half2*)&u1.y);
            __half2 vz = __hadd2(*(__half2*)&u0.z, *(__half2*)&u1.z);
            __half2 vw = __hadd2(*(__half2*)&u0.w, *(__half2*)&u1.w);
            float2 f;
            f = __half22float2(vx); acc[0] += f.x; acc[1] += f.y;
            f = __half22float2(vy); acc[2] += f.x; acc[3] += f.y;
            f = __half22float2(vz); acc[4] += f.x; acc[5] += f.y;
            f = __half22float2(vw); acc[6] += f.x; acc[7] += f.y;
        }
        // remainder: 2 edges per iteration (exact fp32 path)
        for (; t < n; t += 2) {
            int e = t + sel;
            int s = __shfl_sync(0xffffffffu, c, e < 31 ? e : 31);
            if (e < n) {
                uint4 u = hp[s * 16 + hl];
                float2 f;
                f = __half22float2(*(__half2*)&u.x); acc[0] += f.x; acc[1] += f.y;
                f = __half22float2(*(__half2*)&u.y); acc[2] += f.x; acc[3] += f.y;
                f = __half22float2(*(__half2*)&u.z); acc[4] += f.x; acc[5] += f.y;
                f = __half22float2(*(__half2*)&u.w); acc[6] += f.x; acc[7] += f.y;
            }
        }
    }
    #pragma unroll
    for (int k = 0; k < 8; k++) acc[k] += __shfl_xor_sync(0xffffffffu, acc[k], 16);

    if (sel == 0) {
        float nd = g_norm_dst[warp];
        __half2 p0 = __floats2half2_rn(acc[0] * nd, acc[1] * nd);
        __half2 p1 = __floats2half2_rn(acc[2] * nd, acc[3] * nd);
        __half2 p2 = __floats2half2_rn(acc[4] * nd, acc[5] * nd);
        __half2 p3 = __floats2half2_rn(acc[6] * nd, acc[7] * nd);
        uint4 o = make_uint4(*(unsigned*)&p0, *(unsigned*)&p1,
                             *(unsigned*)&p2, *(unsigned*)&p3);
        ((uint4*)g_agg)[warp * 16 + hl] = o;
    }
}

// ---------------- FP16 tensor-core GEMM: out = relu(A @ W + b) [* rowscale] ----------------
#define ASH 68   // half2 per A smem row
#define BSH 66   // half2 per B smem row
#define GEMM_SMEM ((128 * ASH + 128 * BSH) * 4)   // 68608 B

template <bool HALF_OUT>
__global__ __launch_bounds__(256, 2) void k_gemm_f16(
    const uint4* __restrict__ A4, const uint2* __restrict__ WT2,
    const float* __restrict__ bias, const float* __restrict__ rowscale,
    void* __restrict__ outp, int M)
{
    extern __shared__ unsigned smem[];
    unsigned* As = smem;                  // [128][ASH] half2
    unsigned* Bs = smem + 128 * ASH;      // [128][BSH] half2, n-major

    const int tid  = threadIdx.x;
    const int wid  = tid >> 5;
    const int lane = tid & 31;
    const int g = lane >> 2;
    const int c = lane & 3;
    const int wm = (wid & 3) * 32;
    const int wn = (wid >> 2) * 64;
    const int row0 = blockIdx.x * 128;

    #pragma unroll
    for (int l = 0; l < 8; l++) {
        int idx = l * 256 + tid;
        int r = idx >> 4;
        int q = idx & 15;
        uint4 u = make_uint4(0u, 0u, 0u, 0u);
        if (row0 + r < M) u = A4[(row0 + r) * 16 + q];
        *(uint4*)&As[r * ASH + q * 4] = u;
    }
    #pragma unroll
    for (int l = 0; l < 16; l++) {
        int idx = l * 256 + tid;
        int n = idx >> 5;
        int q = idx & 31;
        uint2 u = WT2[n * 32 + q];
        *(uint2*)&Bs[n * BSH + q * 2] = u;
    }
    __syncthreads();

    float acc[2][8][4];
    #pragma unroll
    for (int i = 0; i < 2; i++)
        #pragma unroll
        for (int j = 0; j < 8; j++)
            #pragma unroll
            for (int k = 0; k < 4; k++) acc[i][j][k] = 0.f;

    #pragma unroll
    for (int s = 0; s < 8; s++) {
        const int ko = s * 8;
        unsigned a[2][4];
        #pragma unroll
        for (int mt = 0; mt < 2; mt++) {
            int r = wm + mt * 16 + g;
            a[mt][0] = As[r * ASH + ko + c];
            a[mt][1] = As[(r + 8) * ASH + ko + c];
            a[mt][2] = As[r * ASH + ko + c + 4];
            a[mt][3] = As[(r + 8) * ASH + ko + c + 4];
        }
        #pragma unroll
        for (int nt = 0; nt < 8; nt++) {
            int col = wn + nt * 8 + g;
            unsigned b0 = Bs[col * BSH + ko + c];
            unsigned b1 = Bs[col * BSH + ko + c + 4];
            #pragma unroll
            for (int mt = 0; mt < 2; mt++) {
                asm volatile(
                    "mma.sync.aligned.m16n8k16.row.col.f32.f16.f16.f32 "
                    "{%0,%1,%2,%3}, {%4,%5,%6,%7}, {%8,%9}, {%0,%1,%2,%3};\n"
                    : "+f"(acc[mt][nt][0]), "+f"(acc[mt][nt][1]),
                      "+f"(acc[mt][nt][2]), "+f"(acc[mt][nt][3])
                    : "r"(a[mt][0]), "r"(a[mt][1]), "r"(a[mt][2]), "r"(a[mt][3]),
                      "r"(b0), "r"(b1));
            }
        }
    }

    const int c2 = c * 2;
    #pragma unroll
    for (int nt = 0; nt < 8; nt++) {
        int col = wn + nt * 8 + c2;
        float bi0 = bias[col], bi1 = bias[col + 1];
        #pragma unroll
        for (int mt = 0; mt < 2; mt++) {
            int r = row0 + wm + mt * 16 + g;
            if (r < M) {
                float rs = rowscale ? rowscale[r] : 1.0f;
                float ox = fmaxf(acc[mt][nt][0] + bi0, 0.f) * rs;
                float oy = fmaxf(acc[mt][nt][1] + bi1, 0.f) * rs;
                if (HALF_OUT)
                    ((__half2*)outp)[r * 64 + (col >> 1)] = __floats2half2_rn(ox, oy);
                else
                    ((float2*)outp)[r * 64 + (col >> 1)] = make_float2(ox, oy);
            }
            int r2 = r + 8;
            if (r2 < M) {
                float rs = rowscale ? rowscale[r2] : 1.0f;
                float ox = fmaxf(acc[mt][nt][2] + bi0, 0.f) * rs;
                float oy = fmaxf(acc[mt][nt][3] + bi1, 0.f) * rs;
                if (HALF_OUT)
                    ((__half2*)outp)[r2 * 64 + (col >> 1)] = __floats2half2_rn(ox, oy);
                else
                    ((float2*)outp)[r2 * 64 + (col >> 1)] = make_float2(ox, oy);
            }
        }
    }
}

// ---------------- launch (single stream) ----------------
extern "C" void kernel_launch(void* const* d_in, const int* in_sizes, int n_in,
                              void* d_out, int out_size)
{
    const int*   batch = (const int*)d_in[0];
    const int*   src   = (const int*)d_in[1];
    const int*   dst   = (const int*)d_in[2];
    const float* emb   = (const float*)d_in[3];
    const float* W1    = (const float*)d_in[4];
    const float* b1    = (const float*)d_in[5];
    const float* W2    = (const float*)d_in[6];
    const float* b2    = (const float*)d_in[7];
    const float* W3    = (const float*)d_in[8];
    const float* b3    = (const float*)d_in[9];

    __half2* hbuf;   cudaGetSymbolAddress((void**)&hbuf, g_hh);
    __half2* aggbuf; cudaGetSymbolAddress((void**)&aggbuf, g_agg);
    unsigned* wt;    cudaGetSymbolAddress((void**)&wt, g_wt);
    int* degp;       cudaGetSymbolAddress((void**)&degp, g_deg);
    float* nsrc;     cudaGetSymbolAddress((void**)&nsrc, g_norm_src);

    cudaFuncSetAttribute(k_gemm_f16<true>,
                         cudaFuncAttributeMaxDynamicSharedMemorySize, GEMM_SMEM);
    cudaFuncSetAttribute(k_gemm_f16<false>,
                         cudaFuncAttributeMaxDynamicSharedMemorySize, GEMM_SMEM);

    const int scan_blocks = (NN + 1023) / 1024;   // 49

    cudaMemsetAsync(degp, 0, 2 * NN * sizeof(int), 0);
    k_setup1<<<WCONV_BLOCKS + DEG_BLOCKS, 256>>>((const int4*)src, (const int4*)dst,
                                                 W1, W2, W3);
    k_scan1n<<<scan_blocks, 1024>>>();
    k_scan3<<<(NN + 255) / 256, 256>>>();
    k_h0fill<<<FILL_BLOCKS + H0_BLOCKS, 256>>>(batch, (const float4*)emb,
                                               (const int4*)src, (const int4*)dst);

    const int gemm_grid = (NN + 127) / 128;       // 391
    const int spmm_grid = (NN + 7) / 8;

    // layer 1
    k_spmm<<<spmm_grid, 256>>>();
    k_gemm_f16<true><<<gemm_grid, 256, GEMM_SMEM>>>((const uint4*)aggbuf,
                                                    (const uint2*)wt, b1,
                                                    nsrc, hbuf, NN);
    // layer 2
    k_spmm<<<spmm_grid, 256>>>();
    k_gemm_f16<true><<<gemm_grid, 256, GEMM_SMEM>>>((const uint4*)aggbuf,
                                                    (const uint2*)(wt + 8192), b2,
                                                    nsrc, hbuf, NN);
    // layer 3 -> d_out (fp32, no rowscale)
    k_spmm<<<spmm_grid, 256>>>();
    k_gemm_f16<false><<<gemm_grid, 256, GEMM_SMEM>>>((const uint4*)aggbuf,
                                                     (const uint2*)(wt + 16384), b3,
                                                     nullptr, d_out, NN);
}